// round 2
// baseline (speedup 1.0000x reference)
#include <cuda_runtime.h>
#include <cstdint>

// Problem constants: B=8, S=2048 -> T=16384 tokens, D=1024, F=4096, E=8
#define T_TOK 16384
#define D_DIM 1024
#define F_DIM 4096
#define E_NUM 8
#define EPSV  1e-6f

// ---------------- scratch (device globals; no runtime allocation) ----------
__device__ float g_normed[(size_t)T_TOK * D_DIM];   // 64 MB
__device__ float g_H[(size_t)T_TOK * F_DIM];        // 256 MB
__device__ float g_tp[T_TOK];
__device__ int   g_cnt[E_NUM];
__device__ int   g_list[E_NUM * T_TOK];

// ---------------- f32x2 packed helpers ------------------------------------
#define FMA_F32X2(acc, a, b) \
    asm("fma.rn.f32x2 %0, %1, %2, %0;" : "+l"(acc) : "l"(a), "l"(b))

__device__ __forceinline__ unsigned long long pack_dup(float v) {
    unsigned long long r;
    unsigned int u = __float_as_uint(v);
    asm("mov.b64 %0, {%1, %1};" : "=l"(r) : "r"(u));
    return r;
}
__device__ __forceinline__ void unpack2(unsigned long long p, float& lo, float& hi) {
    unsigned int a, b;
    asm("mov.b64 {%0, %1}, %2;" : "=r"(a), "=r"(b) : "l"(p));
    lo = __uint_as_float(a);
    hi = __uint_as_float(b);
}

// ---------------- kernel 0: zero expert counts -----------------------------
__global__ void k_zero() {
    if (threadIdx.x < E_NUM) g_cnt[threadIdx.x] = 0;
}

// ---------------- kernel 1: RMSNorm + router + scatter ---------------------
// grid: T_TOK blocks x 128 threads. Each block = one token.
__global__ void k_norm_router(const float* __restrict__ x,
                              const float* __restrict__ lnw,
                              const float* __restrict__ rw,
                              float* __restrict__ out_logits,
                              float* __restrict__ out_idx) {
    const int tok = blockIdx.x;
    const int tid = threadIdx.x;  // 0..127, each owns 8 consecutive d
    const size_t base = (size_t)tok * D_DIM + tid * 8;

    float4 v0 = *reinterpret_cast<const float4*>(x + base);
    float4 v1 = *reinterpret_cast<const float4*>(x + base + 4);

    float ss = v0.x * v0.x + v0.y * v0.y + v0.z * v0.z + v0.w * v0.w +
               v1.x * v1.x + v1.y * v1.y + v1.z * v1.z + v1.w * v1.w;
    #pragma unroll
    for (int o = 16; o > 0; o >>= 1) ss += __shfl_xor_sync(0xFFFFFFFFu, ss, o);

    __shared__ float swarp[4];
    if ((tid & 31) == 0) swarp[tid >> 5] = ss;
    __syncthreads();
    float var = (swarp[0] + swarp[1] + swarp[2] + swarp[3]) * (1.0f / D_DIM);
    float rs = rsqrtf(var + EPSV);

    float4 w0 = *reinterpret_cast<const float4*>(lnw + tid * 8);
    float4 w1 = *reinterpret_cast<const float4*>(lnw + tid * 8 + 4);

    float n[8];
    n[0] = v0.x * rs * w0.x;  n[1] = v0.y * rs * w0.y;
    n[2] = v0.z * rs * w0.z;  n[3] = v0.w * rs * w0.w;
    n[4] = v1.x * rs * w1.x;  n[5] = v1.y * rs * w1.y;
    n[6] = v1.z * rs * w1.z;  n[7] = v1.w * rs * w1.w;

    *reinterpret_cast<float4*>(g_normed + base)     = make_float4(n[0], n[1], n[2], n[3]);
    *reinterpret_cast<float4*>(g_normed + base + 4) = make_float4(n[4], n[5], n[6], n[7]);

    // router partial: acc[e] += n[d] * rw[d][e]  (rw is [D][E] row-major)
    float acc[E_NUM];
    #pragma unroll
    for (int e = 0; e < E_NUM; e++) acc[e] = 0.0f;
    #pragma unroll
    for (int i = 0; i < 8; i++) {
        const float* r = rw + (size_t)(tid * 8 + i) * E_NUM;
        float4 r0 = *reinterpret_cast<const float4*>(r);
        float4 r1 = *reinterpret_cast<const float4*>(r + 4);
        acc[0] += n[i] * r0.x;  acc[1] += n[i] * r0.y;
        acc[2] += n[i] * r0.z;  acc[3] += n[i] * r0.w;
        acc[4] += n[i] * r1.x;  acc[5] += n[i] * r1.y;
        acc[6] += n[i] * r1.z;  acc[7] += n[i] * r1.w;
    }
    #pragma unroll
    for (int e = 0; e < E_NUM; e++) {
        #pragma unroll
        for (int o = 16; o > 0; o >>= 1)
            acc[e] += __shfl_xor_sync(0xFFFFFFFFu, acc[e], o);
    }
    __shared__ float sacc[4][E_NUM];
    if ((tid & 31) == 0) {
        #pragma unroll
        for (int e = 0; e < E_NUM; e++) sacc[tid >> 5][e] = acc[e];
    }
    __syncthreads();
    if (tid == 0) {
        float l[E_NUM];
        #pragma unroll
        for (int e = 0; e < E_NUM; e++)
            l[e] = sacc[0][e] + sacc[1][e] + sacc[2][e] + sacc[3][e];
        float m = l[0];
        int arg = 0;
        #pragma unroll
        for (int e = 1; e < E_NUM; e++)
            if (l[e] > m) { m = l[e]; arg = e; }  // first-max like jnp.argmax
        float s = 0.0f;
        #pragma unroll
        for (int e = 0; e < E_NUM; e++) s += expf(l[e] - m);
        g_tp[tok] = 1.0f / s;  // top prob = exp(0)/sum

        if (out_logits) {
            #pragma unroll
            for (int e = 0; e < E_NUM; e++)
                out_logits[(size_t)tok * E_NUM + e] = l[e];
        }
        if (out_idx) out_idx[tok] = (float)arg;

        int pos = atomicAdd(&g_cnt[arg], 1);
        g_list[arg * T_TOK + pos] = tok;
    }
}

// ---------------- grouped GEMM config --------------------------------------
#define TM 128
#define TN 128
#define TKK 8
// 256 threads, 16x16 layout, 8x8 micro-tile; accumulators are packed f32x2
// row-pairs: acc[ip][j] = (C[2ip][j], C[2ip+1][j])
// Mainloop is software-pipelined: next k-block's global loads are issued
// immediately after the smem-publish barrier, hiding LDG latency behind the
// 256 FMA2 instructions of the compute phase.

// GEMM1: H[tok, n] = relu( sum_d normed[tok][d] * wi[e][d][n] )
__global__ void __launch_bounds__(256)
k_gemm1(const float* __restrict__ W) {
    const int e = blockIdx.z;
    const int cnt = g_cnt[e];
    const int m0 = blockIdx.y * TM;
    if (m0 >= cnt) return;
    const int n0 = blockIdx.x * TN;

    __shared__ float As[TKK][TM];
    __shared__ float Bs[TKK][TN];
    __shared__ int stok[TM];

    const int tid = threadIdx.x;
    const int tx = tid & 15, ty = tid >> 4;

    if (tid < TM) {
        int mi = m0 + tid;
        stok[tid] = (mi < cnt) ? g_list[e * T_TOK + mi] : -1;
    }
    __syncthreads();

    // A loader: pair (m, half) ; B loader: (k, n4)
    const int am = tid >> 1;
    const int ah = (tid & 1) * 4;
    const int atok = stok[am];
    const float* Aptr = g_normed + (size_t)(atok >= 0 ? atok : 0) * D_DIM + ah;
    const int bk = tid >> 5;
    const int bn = (tid & 31) * 4;
    const float* Bptr = W + (size_t)e * D_DIM * F_DIM + (size_t)bk * F_DIM + n0 + bn;

    unsigned long long acc[4][8];
    #pragma unroll
    for (int i = 0; i < 4; i++)
        #pragma unroll
        for (int j = 0; j < 8; j++) acc[i][j] = 0ULL;

    // prologue: fetch k-block 0
    float4 av = *reinterpret_cast<const float4*>(Aptr);
    float4 bv = *reinterpret_cast<const float4*>(Bptr);

    for (int k0 = 0; k0 < D_DIM; k0 += TKK) {
        __syncthreads();  // previous compute done reading smem
        As[ah + 0][am] = av.x; As[ah + 1][am] = av.y;
        As[ah + 2][am] = av.z; As[ah + 3][am] = av.w;
        *reinterpret_cast<float4*>(&Bs[bk][bn]) = bv;
        __syncthreads();

        // prefetch next k-block while computing on this one
        if (k0 + TKK < D_DIM) {
            av = *reinterpret_cast<const float4*>(Aptr + k0 + TKK);
            bv = *reinterpret_cast<const float4*>(Bptr + (size_t)(k0 + TKK) * F_DIM);
        }

        #pragma unroll
        for (int k = 0; k < TKK; k++) {
            const unsigned long long* Ap =
                reinterpret_cast<const unsigned long long*>(&As[k][ty * 8]);
            unsigned long long a0 = Ap[0], a1 = Ap[1], a2 = Ap[2], a3 = Ap[3];
            float4 bq0 = *reinterpret_cast<const float4*>(&Bs[k][tx * 8]);
            float4 bq1 = *reinterpret_cast<const float4*>(&Bs[k][tx * 8 + 4]);
            unsigned long long b2[8];
            b2[0] = pack_dup(bq0.x); b2[1] = pack_dup(bq0.y);
            b2[2] = pack_dup(bq0.z); b2[3] = pack_dup(bq0.w);
            b2[4] = pack_dup(bq1.x); b2[5] = pack_dup(bq1.y);
            b2[6] = pack_dup(bq1.z); b2[7] = pack_dup(bq1.w);
            #pragma unroll
            for (int j = 0; j < 8; j++) {
                FMA_F32X2(acc[0][j], a0, b2[j]);
                FMA_F32X2(acc[1][j], a1, b2[j]);
                FMA_F32X2(acc[2][j], a2, b2[j]);
                FMA_F32X2(acc[3][j], a3, b2[j]);
            }
        }
    }

    // epilogue: relu, scatter by token
    #pragma unroll
    for (int ip = 0; ip < 4; ip++) {
        float lo[8], hi[8];
        #pragma unroll
        for (int j = 0; j < 8; j++) unpack2(acc[ip][j], lo[j], hi[j]);
        int r0 = ty * 8 + 2 * ip;
        int t0 = stok[r0], t1 = stok[r0 + 1];
        if (t0 >= 0) {
            float* o = g_H + (size_t)t0 * F_DIM + n0 + tx * 8;
            *reinterpret_cast<float4*>(o) = make_float4(
                fmaxf(lo[0], 0.f), fmaxf(lo[1], 0.f), fmaxf(lo[2], 0.f), fmaxf(lo[3], 0.f));
            *reinterpret_cast<float4*>(o + 4) = make_float4(
                fmaxf(lo[4], 0.f), fmaxf(lo[5], 0.f), fmaxf(lo[6], 0.f), fmaxf(lo[7], 0.f));
        }
        if (t1 >= 0) {
            float* o = g_H + (size_t)t1 * F_DIM + n0 + tx * 8;
            *reinterpret_cast<float4*>(o) = make_float4(
                fmaxf(hi[0], 0.f), fmaxf(hi[1], 0.f), fmaxf(hi[2], 0.f), fmaxf(hi[3], 0.f));
            *reinterpret_cast<float4*>(o + 4) = make_float4(
                fmaxf(hi[4], 0.f), fmaxf(hi[5], 0.f), fmaxf(hi[6], 0.f), fmaxf(hi[7], 0.f));
        }
    }
}

// GEMM2: out[tok, n] = hidden[tok, n] + tp[tok] * sum_f H[tok][f] * wo[e][f][n]
__global__ void __launch_bounds__(256)
k_gemm2(const float* __restrict__ W,
        const float* __restrict__ hidden,
        float* __restrict__ out) {
    const int e = blockIdx.z;
    const int cnt = g_cnt[e];
    const int m0 = blockIdx.y * TM;
    if (m0 >= cnt) return;
    const int n0 = blockIdx.x * TN;

    __shared__ float As[TKK][TM];
    __shared__ float Bs[TKK][TN];
    __shared__ int   stok[TM];
    __shared__ float stp[TM];

    const int tid = threadIdx.x;
    const int tx = tid & 15, ty = tid >> 4;

    if (tid < TM) {
        int mi = m0 + tid;
        int tk = (mi < cnt) ? g_list[e * T_TOK + mi] : -1;
        stok[tid] = tk;
        stp[tid] = (tk >= 0) ? g_tp[tk] : 0.0f;
    }
    __syncthreads();

    const int am = tid >> 1;
    const int ah = (tid & 1) * 4;
    const int atok = stok[am];
    const float* Aptr = g_H + (size_t)(atok >= 0 ? atok : 0) * F_DIM + ah;
    const int bk = tid >> 5;
    const int bn = (tid & 31) * 4;
    const float* Bptr = W + (size_t)e * F_DIM * D_DIM + (size_t)bk * D_DIM + n0 + bn;

    unsigned long long acc[4][8];
    #pragma unroll
    for (int i = 0; i < 4; i++)
        #pragma unroll
        for (int j = 0; j < 8; j++) acc[i][j] = 0ULL;

    float4 av = *reinterpret_cast<const float4*>(Aptr);
    float4 bv = *reinterpret_cast<const float4*>(Bptr);

    for (int k0 = 0; k0 < F_DIM; k0 += TKK) {
        __syncthreads();
        As[ah + 0][am] = av.x; As[ah + 1][am] = av.y;
        As[ah + 2][am] = av.z; As[ah + 3][am] = av.w;
        *reinterpret_cast<float4*>(&Bs[bk][bn]) = bv;
        __syncthreads();

        if (k0 + TKK < F_DIM) {
            av = *reinterpret_cast<const float4*>(Aptr + k0 + TKK);
            bv = *reinterpret_cast<const float4*>(Bptr + (size_t)(k0 + TKK) * D_DIM);
        }

        #pragma unroll
        for (int k = 0; k < TKK; k++) {
            const unsigned long long* Ap =
                reinterpret_cast<const unsigned long long*>(&As[k][ty * 8]);
            unsigned long long a0 = Ap[0], a1 = Ap[1], a2 = Ap[2], a3 = Ap[3];
            float4 bq0 = *reinterpret_cast<const float4*>(&Bs[k][tx * 8]);
            float4 bq1 = *reinterpret_cast<const float4*>(&Bs[k][tx * 8 + 4]);
            unsigned long long b2[8];
            b2[0] = pack_dup(bq0.x); b2[1] = pack_dup(bq0.y);
            b2[2] = pack_dup(bq0.z); b2[3] = pack_dup(bq0.w);
            b2[4] = pack_dup(bq1.x); b2[5] = pack_dup(bq1.y);
            b2[6] = pack_dup(bq1.z); b2[7] = pack_dup(bq1.w);
            #pragma unroll
            for (int j = 0; j < 8; j++) {
                FMA_F32X2(acc[0][j], a0, b2[j]);
                FMA_F32X2(acc[1][j], a1, b2[j]);
                FMA_F32X2(acc[2][j], a2, b2[j]);
                FMA_F32X2(acc[3][j], a3, b2[j]);
            }
        }
    }

    #pragma unroll
    for (int ip = 0; ip < 4; ip++) {
        float lo[8], hi[8];
        #pragma unroll
        for (int j = 0; j < 8; j++) unpack2(acc[ip][j], lo[j], hi[j]);
        int r0 = ty * 8 + 2 * ip;
        int t0 = stok[r0], t1 = stok[r0 + 1];
        if (t0 >= 0) {
            float tp = stp[r0];
            const float* hp = hidden + (size_t)t0 * D_DIM + n0 + tx * 8;
            float* op = out + (size_t)t0 * D_DIM + n0 + tx * 8;
            float4 h0 = *reinterpret_cast<const float4*>(hp);
            float4 h1 = *reinterpret_cast<const float4*>(hp + 4);
            *reinterpret_cast<float4*>(op) = make_float4(
                h0.x + tp * lo[0], h0.y + tp * lo[1], h0.z + tp * lo[2], h0.w + tp * lo[3]);
            *reinterpret_cast<float4*>(op + 4) = make_float4(
                h1.x + tp * lo[4], h1.y + tp * lo[5], h1.z + tp * lo[6], h1.w + tp * lo[7]);
        }
        if (t1 >= 0) {
            float tp = stp[r0 + 1];
            const float* hp = hidden + (size_t)t1 * D_DIM + n0 + tx * 8;
            float* op = out + (size_t)t1 * D_DIM + n0 + tx * 8;
            float4 h0 = *reinterpret_cast<const float4*>(hp);
            float4 h1 = *reinterpret_cast<const float4*>(hp + 4);
            *reinterpret_cast<float4*>(op) = make_float4(
                h0.x + tp * hi[0], h0.y + tp * hi[1], h0.z + tp * hi[2], h0.w + tp * hi[3]);
            *reinterpret_cast<float4*>(op + 4) = make_float4(
                h1.x + tp * hi[4], h1.y + tp * hi[5], h1.z + tp * hi[6], h1.w + tp * hi[7]);
        }
    }
}

// ---------------- launch ----------------------------------------------------
extern "C" void kernel_launch(void* const* d_in, const int* in_sizes, int n_in,
                              void* d_out, int out_size) {
    const float* hidden = (const float*)d_in[0];
    const float* lnw    = (const float*)d_in[1];
    const float* rw     = (const float*)d_in[2];
    const float* wi     = (const float*)d_in[3];
    const float* wo     = (const float*)d_in[4];
    float* out = (float*)d_out;

    const int main_sz = T_TOK * D_DIM;           // 16777216
    float* out_logits = nullptr;
    float* out_idx = nullptr;
    if (out_size >= main_sz + T_TOK * E_NUM)
        out_logits = out + main_sz;
    if (out_size >= main_sz + T_TOK * E_NUM + T_TOK)
        out_idx = out + main_sz + T_TOK * E_NUM;

    k_zero<<<1, 32>>>();
    k_norm_router<<<T_TOK, 128>>>(hidden, lnw, rw, out_logits, out_idx);

    dim3 g1(F_DIM / TN, T_TOK / TM, E_NUM);
    k_gemm1<<<g1, 256>>>(wi);

    dim3 g2(D_DIM / TN, T_TOK / TM, E_NUM);
    k_gemm2<<<g2, 256>>>(wo, hidden, out);
}

// round 7
// speedup vs baseline: 2.0232x; 2.0232x over previous
#include <cuda_runtime.h>
#include <cuda_bf16.h>
#include <cstdint>

// Problem: B=8,S=2048 -> T=16384 tokens, D=1024, F=4096, E=8
// R7: identical to R5/R6 except `#pragma unroll 1` on the k_mma mainloop.
// Theory: constexpr trip count (64 for GEMM2) was fully unrolled -> ~50K-instr
// function -> ptxas register-allocation blowup -> build timeout -> opaque
// "container failed twice". Cap the unroll; everything else unchanged.
#define T_TOK 16384
#define D_DIM 1024
#define F_DIM 4096
#define E_NUM 8
#define EPSV  1e-6f
#define MP_MAX 17408   // 16384 + 8*127 padded, rounded up

// ---------------- device-global scratch (no runtime allocation) -------------
__device__ float g_normed[(size_t)T_TOK * D_DIM];
__device__ float g_tp[T_TOK];
__device__ int   g_exp[T_TOK];
__device__ int   g_pos[T_TOK];
__device__ int   g_cnt[E_NUM];
__device__ int   g_pcnt[E_NUM];
__device__ int   g_off[E_NUM];
__device__ int   g_rowtok[MP_MAX];
__device__ float g_rowtp[MP_MAX];
__device__ __nv_bfloat16 g_Xh[(size_t)MP_MAX * D_DIM];
__device__ __nv_bfloat16 g_Xl[(size_t)MP_MAX * D_DIM];
__device__ __nv_bfloat16 g_Hh[(size_t)MP_MAX * F_DIM];
__device__ __nv_bfloat16 g_Hl[(size_t)MP_MAX * F_DIM];
__device__ __nv_bfloat16 g_wiTh[(size_t)E_NUM * F_DIM * D_DIM];
__device__ __nv_bfloat16 g_wiTl[(size_t)E_NUM * F_DIM * D_DIM];
__device__ __nv_bfloat16 g_woTh[(size_t)E_NUM * D_DIM * F_DIM];
__device__ __nv_bfloat16 g_woTl[(size_t)E_NUM * D_DIM * F_DIM];

// ---------------- PTX helpers (sm_80-era only: safe on sm_100 target) -------
__device__ __forceinline__ uint32_t smem_u32(const void* p) {
    uint32_t a;
    asm("{ .reg .u64 t; cvta.to.shared.u64 t, %1; cvt.u32.u64 %0, t; }" : "=r"(a) : "l"(p));
    return a;
}
#define CP16(dst, src) \
    asm volatile("cp.async.cg.shared.global [%0], [%1], 16;" :: "r"(dst), "l"(src))
#define CP_COMMIT() asm volatile("cp.async.commit_group;" ::: "memory")
#define CP_WAIT1()  asm volatile("cp.async.wait_group 1;" ::: "memory")
#define CP_WAIT0()  asm volatile("cp.async.wait_group 0;" ::: "memory")
#define LDSM4(r0, r1, r2, r3, addr) \
    asm volatile("ldmatrix.sync.aligned.m8n8.x4.shared.b16 {%0,%1,%2,%3}, [%4];" \
                 : "=r"(r0), "=r"(r1), "=r"(r2), "=r"(r3) : "r"(addr))
#define LDSM2(r0, r1, addr) \
    asm volatile("ldmatrix.sync.aligned.m8n8.x2.shared.b16 {%0,%1}, [%2];" \
                 : "=r"(r0), "=r"(r1) : "r"(addr))
#define MMA_BF16(d, a, b) \
    asm volatile("mma.sync.aligned.m16n8k16.row.col.f32.bf16.bf16.f32 " \
                 "{%0,%1,%2,%3}, {%4,%5,%6,%7}, {%8,%9}, {%0,%1,%2,%3};" \
                 : "+f"((d)[0]), "+f"((d)[1]), "+f"((d)[2]), "+f"((d)[3]) \
                 : "r"((a)[0]), "r"((a)[1]), "r"((a)[2]), "r"((a)[3]), \
                   "r"((b)[0]), "r"((b)[1]))

__device__ __forceinline__ uint32_t packbf2(float lo_v, float hi_v) {
    uint32_t r;
    asm("cvt.rn.bf16x2.f32 %0, %1, %2;" : "=r"(r) : "f"(hi_v), "f"(lo_v));
    return r;
}

// ---------------- kernel: zero counts ---------------------------------------
__global__ void k_zero() {
    if (threadIdx.x < E_NUM) g_cnt[threadIdx.x] = 0;
}

// ---------------- kernel: transpose + fp32->bf16 hi/lo split ----------------
// in: [E][R][C] fp32 -> out (which=0: g_wiT*, which=1: g_woT*): [E][C][R] bf16
__global__ void k_wt(const float* __restrict__ in, int R, int C, int which) {
    __shared__ float t[32][33];
    const int e = blockIdx.z;
    const int c0 = blockIdx.x * 32, r0 = blockIdx.y * 32;
    const int tx = threadIdx.x, ty = threadIdx.y;  // 32 x 8
    const float* ip = in + (size_t)e * R * C;
    #pragma unroll
    for (int j = 0; j < 4; j++)
        t[ty + 8 * j][tx] = ip[(size_t)(r0 + ty + 8 * j) * C + c0 + tx];
    __syncthreads();
    __nv_bfloat16* oh = which ? g_woTh : g_wiTh;
    __nv_bfloat16* ol = which ? g_woTl : g_wiTl;
    const size_t ob = (size_t)e * R * C;
    #pragma unroll
    for (int j = 0; j < 4; j++) {
        float v = t[tx][ty + 8 * j];
        __nv_bfloat16 h = __float2bfloat16(v);
        float l = v - __bfloat162float(h);
        size_t o = ob + (size_t)(c0 + ty + 8 * j) * R + r0 + tx;
        oh[o] = h;
        ol[o] = __float2bfloat16(l);
    }
}

// ---------------- kernel: RMSNorm + router + routing metadata ---------------
__global__ void k_norm_router(const float* __restrict__ x,
                              const float* __restrict__ lnw,
                              const float* __restrict__ rw,
                              float* __restrict__ out_logits,
                              float* __restrict__ out_idx) {
    const int tok = blockIdx.x;
    const int tid = threadIdx.x;
    const size_t base = (size_t)tok * D_DIM + tid * 8;

    float4 v0 = *reinterpret_cast<const float4*>(x + base);
    float4 v1 = *reinterpret_cast<const float4*>(x + base + 4);

    float ss = v0.x * v0.x + v0.y * v0.y + v0.z * v0.z + v0.w * v0.w +
               v1.x * v1.x + v1.y * v1.y + v1.z * v1.z + v1.w * v1.w;
    #pragma unroll
    for (int o = 16; o > 0; o >>= 1) ss += __shfl_xor_sync(0xFFFFFFFFu, ss, o);

    __shared__ float swarp[4];
    if ((tid & 31) == 0) swarp[tid >> 5] = ss;
    __syncthreads();
    float var = (swarp[0] + swarp[1] + swarp[2] + swarp[3]) * (1.0f / D_DIM);
    float rs = rsqrtf(var + EPSV);

    float4 w0 = *reinterpret_cast<const float4*>(lnw + tid * 8);
    float4 w1 = *reinterpret_cast<const float4*>(lnw + tid * 8 + 4);

    float n[8];
    n[0] = v0.x * rs * w0.x;  n[1] = v0.y * rs * w0.y;
    n[2] = v0.z * rs * w0.z;  n[3] = v0.w * rs * w0.w;
    n[4] = v1.x * rs * w1.x;  n[5] = v1.y * rs * w1.y;
    n[6] = v1.z * rs * w1.z;  n[7] = v1.w * rs * w1.w;

    *reinterpret_cast<float4*>(g_normed + base)     = make_float4(n[0], n[1], n[2], n[3]);
    *reinterpret_cast<float4*>(g_normed + base + 4) = make_float4(n[4], n[5], n[6], n[7]);

    float acc[E_NUM];
    #pragma unroll
    for (int e = 0; e < E_NUM; e++) acc[e] = 0.0f;
    #pragma unroll
    for (int i = 0; i < 8; i++) {
        const float* r = rw + (size_t)(tid * 8 + i) * E_NUM;
        float4 r0 = *reinterpret_cast<const float4*>(r);
        float4 r1 = *reinterpret_cast<const float4*>(r + 4);
        acc[0] += n[i] * r0.x;  acc[1] += n[i] * r0.y;
        acc[2] += n[i] * r0.z;  acc[3] += n[i] * r0.w;
        acc[4] += n[i] * r1.x;  acc[5] += n[i] * r1.y;
        acc[6] += n[i] * r1.z;  acc[7] += n[i] * r1.w;
    }
    #pragma unroll
    for (int e = 0; e < E_NUM; e++) {
        #pragma unroll
        for (int o = 16; o > 0; o >>= 1)
            acc[e] += __shfl_xor_sync(0xFFFFFFFFu, acc[e], o);
    }
    __shared__ float sacc[4][E_NUM];
    if ((tid & 31) == 0) {
        #pragma unroll
        for (int e = 0; e < E_NUM; e++) sacc[tid >> 5][e] = acc[e];
    }
    __syncthreads();
    if (tid == 0) {
        float l[E_NUM];
        #pragma unroll
        for (int e = 0; e < E_NUM; e++)
            l[e] = sacc[0][e] + sacc[1][e] + sacc[2][e] + sacc[3][e];
        float m = l[0];
        int arg = 0;
        #pragma unroll
        for (int e = 1; e < E_NUM; e++)
            if (l[e] > m) { m = l[e]; arg = e; }
        float s = 0.0f;
        #pragma unroll
        for (int e = 0; e < E_NUM; e++) s += expf(l[e] - m);
        g_tp[tok] = 1.0f / s;

        if (out_logits) {
            #pragma unroll
            for (int e = 0; e < E_NUM; e++)
                out_logits[(size_t)tok * E_NUM + e] = l[e];
        }
        if (out_idx) out_idx[tok] = (float)arg;

        g_exp[tok] = arg;
        int pos = atomicAdd(&g_cnt[arg], 1);
        g_pos[tok] = pos;
    }
}

// ---------------- kernel: padded offsets ------------------------------------
__global__ void k_offsets() {
    if (threadIdx.x == 0) {
        int s = 0;
        for (int e = 0; e < E_NUM; e++) {
            g_off[e] = s;
            int p = (g_cnt[e] + 127) & ~127;
            g_pcnt[e] = p;
            s += p;
        }
    }
}

// ---------------- kernel: pack tokens expert-contiguous, bf16 hi/lo ---------
__global__ void k_pack() {
    const int tok = blockIdx.x;
    const int e = g_exp[tok];
    const int dest = g_off[e] + g_pos[tok];
    const int t = threadIdx.x;          // 256 threads x 4 elems

    float4 v = *reinterpret_cast<const float4*>(g_normed + (size_t)tok * D_DIM + t * 4);
    float hx = __bfloat162float(__float2bfloat16(v.x));
    float hy = __bfloat162float(__float2bfloat16(v.y));
    float hz = __bfloat162float(__float2bfloat16(v.z));
    float hw = __bfloat162float(__float2bfloat16(v.w));
    uint2 ph = make_uint2(packbf2(v.x, v.y), packbf2(v.z, v.w));
    uint2 pl = make_uint2(packbf2(v.x - hx, v.y - hy), packbf2(v.z - hz, v.w - hw));

    const size_t o = (size_t)dest * D_DIM + t * 4;
    *reinterpret_cast<uint2*>(reinterpret_cast<char*>(g_Xh) + o * 2) = ph;
    *reinterpret_cast<uint2*>(reinterpret_cast<char*>(g_Xl) + o * 2) = pl;

    if (t == 0) {
        g_rowtok[dest] = tok;
        g_rowtp[dest] = g_tp[tok];
    }
}

// ---------------- kernel: zero padding rows ---------------------------------
__global__ void k_pad() {
    const int e = blockIdx.x;
    const int start = g_off[e] + g_cnt[e];
    const int end = g_off[e] + g_pcnt[e];
    if (start >= end) return;
    for (int r = start + threadIdx.x; r < end; r += blockDim.x) {
        g_rowtok[r] = -1;
        g_rowtp[r] = 0.0f;
    }
    const size_t n = (size_t)(end - start) * D_DIM;
    const size_t b = (size_t)start * D_DIM;
    const __nv_bfloat16 z = __float2bfloat16(0.0f);
    for (size_t i = threadIdx.x; i < n; i += blockDim.x) {
        g_Xh[b + i] = z;
        g_Xl[b + i] = z;
    }
}

// ---------------- mma.sync grouped GEMM -------------------------------------
// CTA tile 128x128, K-chunk 64. 8 warps in 2(M)x4(N), warp tile 64x32.
// SMEM (from 1KB-aligned sb0): buf b at b*65536:
//   Ah@0, Al@16384, Bh@32768, Bl@49152 (each 128 rows x 128B, SW128-swizzled)
// aux: rowtok@131072 (512B), rowtp@131584 (512B)
#define SM_RT  131072
#define SM_RP  131584
#define SM_DYN 133120   // 132096 + 1KB alignment slack

template<int KDIM, bool G1>
__global__ void __launch_bounds__(256, 1)
k_mma(const float* __restrict__ hidden, float* __restrict__ out) {
    const int e = blockIdx.z;
    const int m0 = blockIdx.y * 128;
    if (m0 >= g_pcnt[e]) return;
    const int n0 = blockIdx.x * 128;
    const int mbase = g_off[e] + m0;

    extern __shared__ char smem[];
    const uint32_t sb_raw = smem_u32(smem);
    const uint32_t sb0 = (sb_raw + 1023u) & ~1023u;
    char* sp = smem + (sb0 - sb_raw);

    const int tid = threadIdx.x;
    const int wid = tid >> 5, lane = tid & 31;
    const int wm = (wid & 1) * 64, wn = (wid >> 1) * 32;

    if (!G1 && tid < 128) {
        reinterpret_cast<int*>(sp + SM_RT)[tid] = g_rowtok[mbase + tid];
        reinterpret_cast<float*>(sp + SM_RP)[tid] = g_rowtp[mbase + tid];
    }

    // cp.async geometry: thread owns row r, 64B half of the 128B row
    const int r = tid >> 1, half = tid & 1;
    uint32_t swo[4];
    #pragma unroll
    for (int i = 0; i < 4; i++) {
        uint32_t bo = r * 128 + half * 64 + i * 16;
        swo[i] = bo ^ ((bo >> 3) & 0x70);
    }

    const __nv_bfloat16 *Agh, *Agl, *Bgh, *Bgl;
    if (G1) {
        Agh = g_Xh + (size_t)(mbase + r) * D_DIM + half * 32;
        Agl = g_Xl + (size_t)(mbase + r) * D_DIM + half * 32;
        Bgh = g_wiTh + ((size_t)e * F_DIM + n0 + r) * D_DIM + half * 32;
        Bgl = g_wiTl + ((size_t)e * F_DIM + n0 + r) * D_DIM + half * 32;
    } else {
        Agh = g_Hh + (size_t)(mbase + r) * F_DIM + half * 32;
        Agl = g_Hl + (size_t)(mbase + r) * F_DIM + half * 32;
        Bgh = g_woTh + ((size_t)e * D_DIM + n0 + r) * F_DIM + half * 32;
        Bgl = g_woTl + ((size_t)e * D_DIM + n0 + r) * F_DIM + half * 32;
    }

    float acc[4][4][4];
    #pragma unroll
    for (int mi = 0; mi < 4; mi++)
        #pragma unroll
        for (int ni = 0; ni < 4; ni++)
            #pragma unroll
            for (int q = 0; q < 4; q++) acc[mi][ni][q] = 0.0f;

    // ldmatrix per-lane geometry
    // A frag (m16k16): rows m+(lane&15); k byte-offset +16 for lanes>=16
    // B frag (n8k16):  rows n+(lane&7);  k byte-offset +16 for lanes 8-15
    const int aRow = lane & 15;
    const int aKB = (lane >> 4) * 16;
    const int bRow = lane & 7;
    const int bKB = ((lane >> 3) & 1) * 16;

    auto issue = [&](int c) {
        const uint32_t bb = sb0 + (uint32_t)(c & 1) * 65536u;
        const int ko = c * 64;
        const char* sa_h = reinterpret_cast<const char*>(Agh + ko);
        const char* sa_l = reinterpret_cast<const char*>(Agl + ko);
        const char* sb_h = reinterpret_cast<const char*>(Bgh + ko);
        const char* sb_l = reinterpret_cast<const char*>(Bgl + ko);
        #pragma unroll
        for (int i = 0; i < 4; i++) {
            CP16(bb + 0     + swo[i], sa_h + i * 16);
            CP16(bb + 16384 + swo[i], sa_l + i * 16);
            CP16(bb + 32768 + swo[i], sb_h + i * 16);
            CP16(bb + 49152 + swo[i], sb_l + i * 16);
        }
        CP_COMMIT();
    };

    constexpr int NCH = KDIM / 64;
    issue(0);

    #pragma unroll 1
    for (int c = 0; c < NCH; c++) {
        if (c + 1 < NCH) { issue(c + 1); CP_WAIT1(); }
        else             { CP_WAIT0(); }
        __syncthreads();

        const uint32_t bb = sb0 + (uint32_t)(c & 1) * 65536u;
        #pragma unroll
        for (int s = 0; s < 4; s++) {
            const int kb = s * 32;  // byte offset of this k16 step within the 128B row
            uint32_t ah[4][4], al[4][4], bh[4][2], bl[4][2];
            #pragma unroll
            for (int mi = 0; mi < 4; mi++) {
                int row = wm + mi * 16 + aRow;
                uint32_t ad = bb + row * 128 + ((kb + aKB) ^ ((row & 7) << 4));
                LDSM4(ah[mi][0], ah[mi][1], ah[mi][2], ah[mi][3], ad);
                LDSM4(al[mi][0], al[mi][1], al[mi][2], al[mi][3], ad + 16384);
            }
            #pragma unroll
            for (int ni = 0; ni < 4; ni++) {
                int row = wn + ni * 8 + bRow;
                uint32_t bd = bb + 32768 + row * 128 + ((kb + bKB) ^ ((row & 7) << 4));
                LDSM2(bh[ni][0], bh[ni][1], bd);
                LDSM2(bl[ni][0], bl[ni][1], bd + 16384);
            }
            #pragma unroll
            for (int mi = 0; mi < 4; mi++)
                #pragma unroll
                for (int ni = 0; ni < 4; ni++) {
                    MMA_BF16(acc[mi][ni], ah[mi], bh[ni]);
                    MMA_BF16(acc[mi][ni], ah[mi], bl[ni]);
                    MMA_BF16(acc[mi][ni], al[mi], bh[ni]);
                }
        }
        __syncthreads();
    }

    // epilogue. acc[mi][ni]: rows (wm+mi*16+lane/4, +8), cols wn+ni*8+(lane&3)*2,+1
    if (G1) {
        #pragma unroll
        for (int mi = 0; mi < 4; mi++) {
            const size_t r0g = (size_t)(mbase + wm + mi * 16 + (lane >> 2));
            #pragma unroll
            for (int ni = 0; ni < 4; ni++) {
                const int col = n0 + wn + ni * 8 + (lane & 3) * 2;
                float v0 = fmaxf(acc[mi][ni][0], 0.0f);
                float v1 = fmaxf(acc[mi][ni][1], 0.0f);
                float v2 = fmaxf(acc[mi][ni][2], 0.0f);
                float v3 = fmaxf(acc[mi][ni][3], 0.0f);
                float h0 = __bfloat162float(__float2bfloat16(v0));
                float h1 = __bfloat162float(__float2bfloat16(v1));
                float h2 = __bfloat162float(__float2bfloat16(v2));
                float h3 = __bfloat162float(__float2bfloat16(v3));
                *reinterpret_cast<uint32_t*>(reinterpret_cast<char*>(g_Hh) +
                    (r0g * F_DIM + col) * 2) = packbf2(v0, v1);
                *reinterpret_cast<uint32_t*>(reinterpret_cast<char*>(g_Hl) +
                    (r0g * F_DIM + col) * 2) = packbf2(v0 - h0, v1 - h1);
                *reinterpret_cast<uint32_t*>(reinterpret_cast<char*>(g_Hh) +
                    ((r0g + 8) * F_DIM + col) * 2) = packbf2(v2, v3);
                *reinterpret_cast<uint32_t*>(reinterpret_cast<char*>(g_Hl) +
                    ((r0g + 8) * F_DIM + col) * 2) = packbf2(v2 - h2, v3 - h3);
            }
        }
    } else {
        #pragma unroll
        for (int mi = 0; mi < 4; mi++) {
            const int idx = wm + mi * 16 + (lane >> 2);
            const int t0 = reinterpret_cast<int*>(sp + SM_RT)[idx];
            const int t1 = reinterpret_cast<int*>(sp + SM_RT)[idx + 8];
            const float p0 = reinterpret_cast<float*>(sp + SM_RP)[idx];
            const float p1 = reinterpret_cast<float*>(sp + SM_RP)[idx + 8];
            #pragma unroll
            for (int ni = 0; ni < 4; ni++) {
                const int col = n0 + wn + ni * 8 + (lane & 3) * 2;
                if (t0 >= 0) {
                    const size_t o = (size_t)t0 * D_DIM + col;
                    float2 h = *reinterpret_cast<const float2*>(hidden + o);
                    float2 v = make_float2(h.x + p0 * acc[mi][ni][0],
                                           h.y + p0 * acc[mi][ni][1]);
                    *reinterpret_cast<float2*>(out + o) = v;
                }
                if (t1 >= 0) {
                    const size_t o = (size_t)t1 * D_DIM + col;
                    float2 h = *reinterpret_cast<const float2*>(hidden + o);
                    float2 v = make_float2(h.x + p1 * acc[mi][ni][2],
                                           h.y + p1 * acc[mi][ni][3]);
                    *reinterpret_cast<float2*>(out + o) = v;
                }
            }
        }
    }
}

// ---------------- launch ----------------------------------------------------
extern "C" void kernel_launch(void* const* d_in, const int* in_sizes, int n_in,
                              void* d_out, int out_size) {
    const float* hidden = (const float*)d_in[0];
    const float* lnw    = (const float*)d_in[1];
    const float* rw     = (const float*)d_in[2];
    const float* wi     = (const float*)d_in[3];
    const float* wo     = (const float*)d_in[4];
    float* out = (float*)d_out;

    const int main_sz = T_TOK * D_DIM;
    float* out_logits = nullptr;
    float* out_idx = nullptr;
    if (out_size >= main_sz + T_TOK * E_NUM)
        out_logits = out + main_sz;
    if (out_size >= main_sz + T_TOK * E_NUM + T_TOK)
        out_idx = out + main_sz + T_TOK * E_NUM;

    static bool attr_done = false;
    if (!attr_done) {
        cudaFuncSetAttribute(k_mma<D_DIM, true>,
                             cudaFuncAttributeMaxDynamicSharedMemorySize, SM_DYN);
        cudaFuncSetAttribute(k_mma<F_DIM, false>,
                             cudaFuncAttributeMaxDynamicSharedMemorySize, SM_DYN);
        attr_done = true;
    }

    k_zero<<<1, 32>>>();
    k_wt<<<dim3(F_DIM / 32, D_DIM / 32, E_NUM), dim3(32, 8)>>>(wi, D_DIM, F_DIM, 0);
    k_wt<<<dim3(D_DIM / 32, F_DIM / 32, E_NUM), dim3(32, 8)>>>(wo, F_DIM, D_DIM, 1);
    k_norm_router<<<T_TOK, 128>>>(hidden, lnw, rw, out_logits, out_idx);
    k_offsets<<<1, 32>>>();
    k_pack<<<T_TOK, 256>>>();
    k_pad<<<E_NUM, 256>>>();

    k_mma<D_DIM, true><<<dim3(F_DIM / 128, T_TOK / 128, E_NUM), 256, SM_DYN>>>(nullptr, nullptr);
    k_mma<F_DIM, false><<<dim3(D_DIM / 128, T_TOK / 128, E_NUM), 256, SM_DYN>>>(hidden, out);
}

// round 8
// speedup vs baseline: 4.8417x; 2.3931x over previous
#include <cuda_runtime.h>
#include <cuda_fp16.h>
#include <cstdint>

// Problem: B=8,S=2048 -> T=16384 tokens, D=1024, F=4096, E=8
// R8: fp16 single-term GEMM (was bf16 3-term hi/lo split). MMA work /3,
// scratch traffic /2, occupancy 2. 4 launches so ncu captures k_mma.
// Keep `#pragma unroll 1` on the k-chunk mainloop (R7 lesson: full unroll
// of NCH=64 body explodes ptxas -> build timeout).
#define T_TOK 16384
#define D_DIM 1024
#define F_DIM 4096
#define E_NUM 8
#define EPSV  1e-6f
#define MP_MAX 17408

// ---------------- device-global scratch (no runtime allocation) -------------
__device__ float g_tp[T_TOK];
__device__ int   g_exp[T_TOK];
__device__ int   g_cnt[E_NUM];
__device__ int   g_pcnt[E_NUM];
__device__ int   g_off[E_NUM];
__device__ int   g_rowtok[MP_MAX];
__device__ float g_rowtp[MP_MAX];
__device__ __half g_Xtok[(size_t)T_TOK * D_DIM];            // token-indexed fp16 X
__device__ __half g_H[(size_t)MP_MAX * F_DIM];              // expert-row fp16 H
__device__ __half g_wiT[(size_t)E_NUM * F_DIM * D_DIM];     // [E][F][D]
__device__ __half g_woT[(size_t)E_NUM * D_DIM * F_DIM];     // [E][D][F]

// ---------------- PTX helpers ----------------------------------------------
__device__ __forceinline__ uint32_t smem_u32(const void* p) {
    uint32_t a;
    asm("{ .reg .u64 t; cvta.to.shared.u64 t, %1; cvt.u32.u64 %0, t; }" : "=r"(a) : "l"(p));
    return a;
}
#define CP16(dst, src) \
    asm volatile("cp.async.cg.shared.global [%0], [%1], 16;" :: "r"(dst), "l"(src))
// zero-fill variant: copies sz bytes from src, zero-pads to 16
#define CP16Z(dst, src, sz) \
    asm volatile("cp.async.cg.shared.global [%0], [%1], 16, %2;" \
                 :: "r"(dst), "l"(src), "r"(sz))
#define CP_COMMIT() asm volatile("cp.async.commit_group;" ::: "memory")
#define CP_WAIT1()  asm volatile("cp.async.wait_group 1;" ::: "memory")
#define CP_WAIT0()  asm volatile("cp.async.wait_group 0;" ::: "memory")
#define LDSM4(r0, r1, r2, r3, addr) \
    asm volatile("ldmatrix.sync.aligned.m8n8.x4.shared.b16 {%0,%1,%2,%3}, [%4];" \
                 : "=r"(r0), "=r"(r1), "=r"(r2), "=r"(r3) : "r"(addr))
#define LDSM2(r0, r1, addr) \
    asm volatile("ldmatrix.sync.aligned.m8n8.x2.shared.b16 {%0,%1}, [%2];" \
                 : "=r"(r0), "=r"(r1) : "r"(addr))
#define MMA_F16(d, a, b) \
    asm volatile("mma.sync.aligned.m16n8k16.row.col.f32.f16.f16.f32 " \
                 "{%0,%1,%2,%3}, {%4,%5,%6,%7}, {%8,%9}, {%0,%1,%2,%3};" \
                 : "+f"((d)[0]), "+f"((d)[1]), "+f"((d)[2]), "+f"((d)[3]) \
                 : "r"((a)[0]), "r"((a)[1]), "r"((a)[2]), "r"((a)[3]), \
                   "r"((b)[0]), "r"((b)[1]))

// ---------------- kernel 1: fused weight transpose + RMSNorm/router ---------
// grid.x = 32768 (wi tiles) + 32768 (wo tiles) + 16384 (tokens), block 256.
#define WI_TILES 32768   // (F/32)*(D/32)*E
#define WO_TILES 32768   // (D/32)*(F/32)*E
__global__ void __launch_bounds__(256)
k_prep(const float* __restrict__ x,
       const float* __restrict__ lnw,
       const float* __restrict__ rw,
       const float* __restrict__ wi,
       const float* __restrict__ wo,
       float* __restrict__ out_logits,
       float* __restrict__ out_idx) {
    __shared__ float shbuf[32 * 33];
    const int b = blockIdx.x;
    const int tid = threadIdx.x;

    if (b < WI_TILES + WO_TILES) {
        // ---- weight transpose + fp32->fp16: in [E][R][C] -> out [E][C][R]
        const bool is_wi = (b < WI_TILES);
        const int bb = is_wi ? b : b - WI_TILES;
        const int R = is_wi ? D_DIM : F_DIM;
        const int C = is_wi ? F_DIM : D_DIM;
        const int ctiles = C / 32;
        const int e = bb / (ctiles * (R / 32));
        const int rem = bb % (ctiles * (R / 32));
        const int cx = rem % ctiles, ry = rem / ctiles;
        const int c0 = cx * 32, r0 = ry * 32;
        const float* ip = (is_wi ? wi : wo) + (size_t)e * R * C;
        __half* op = (is_wi ? g_wiT : g_woT) + (size_t)e * R * C;
        const int tx = tid & 31, ty = tid >> 5;  // 32 x 8
        #pragma unroll
        for (int j = 0; j < 4; j++)
            shbuf[(ty + 8 * j) * 33 + tx] = ip[(size_t)(r0 + ty + 8 * j) * C + c0 + tx];
        __syncthreads();
        #pragma unroll
        for (int j = 0; j < 4; j++)
            op[(size_t)(c0 + ty + 8 * j) * R + r0 + tx] =
                __float2half(shbuf[tx * 33 + ty + 8 * j]);
        return;
    }

    // ---- RMSNorm + router for one token; 256 threads x 4 elems
    const int tok = b - (WI_TILES + WO_TILES);
    const int lane = tid & 31, wrp = tid >> 5;
    const size_t base = (size_t)tok * D_DIM + tid * 4;
    float4 v = *reinterpret_cast<const float4*>(x + base);

    float ss = v.x * v.x + v.y * v.y + v.z * v.z + v.w * v.w;
    #pragma unroll
    for (int o = 16; o > 0; o >>= 1) ss += __shfl_xor_sync(0xFFFFFFFFu, ss, o);
    if (lane == 0) shbuf[wrp] = ss;
    __syncthreads();
    float var = 0.0f;
    #pragma unroll
    for (int w = 0; w < 8; w++) var += shbuf[w];
    var *= (1.0f / D_DIM);
    const float rs = rsqrtf(var + EPSV);

    float4 w4 = *reinterpret_cast<const float4*>(lnw + tid * 4);
    float n[4] = {v.x * rs * w4.x, v.y * rs * w4.y, v.z * rs * w4.z, v.w * rs * w4.w};

    // fp16 X write (token-indexed)
    __half2 h01 = __floats2half2_rn(n[0], n[1]);
    __half2 h23 = __floats2half2_rn(n[2], n[3]);
    *reinterpret_cast<__half2*>(g_Xtok + base) = h01;
    *reinterpret_cast<__half2*>(g_Xtok + base + 2) = h23;

    // router partials
    float acc[E_NUM];
    #pragma unroll
    for (int e = 0; e < E_NUM; e++) acc[e] = 0.0f;
    #pragma unroll
    for (int i = 0; i < 4; i++) {
        const float* r = rw + (size_t)(tid * 4 + i) * E_NUM;
        float4 r0 = *reinterpret_cast<const float4*>(r);
        float4 r1 = *reinterpret_cast<const float4*>(r + 4);
        acc[0] += n[i] * r0.x;  acc[1] += n[i] * r0.y;
        acc[2] += n[i] * r0.z;  acc[3] += n[i] * r0.w;
        acc[4] += n[i] * r1.x;  acc[5] += n[i] * r1.y;
        acc[6] += n[i] * r1.z;  acc[7] += n[i] * r1.w;
    }
    #pragma unroll
    for (int e = 0; e < E_NUM; e++) {
        #pragma unroll
        for (int o = 16; o > 0; o >>= 1)
            acc[e] += __shfl_xor_sync(0xFFFFFFFFu, acc[e], o);
    }
    __syncthreads();  // shbuf reuse
    if (lane == 0) {
        #pragma unroll
        for (int e = 0; e < E_NUM; e++) shbuf[32 + wrp * E_NUM + e] = acc[e];
    }
    __syncthreads();
    if (tid == 0) {
        float l[E_NUM];
        #pragma unroll
        for (int e = 0; e < E_NUM; e++) {
            float s = 0.0f;
            #pragma unroll
            for (int w = 0; w < 8; w++) s += shbuf[32 + w * E_NUM + e];
            l[e] = s;
        }
        float m = l[0];
        int arg = 0;
        #pragma unroll
        for (int e = 1; e < E_NUM; e++)
            if (l[e] > m) { m = l[e]; arg = e; }
        float s = 0.0f;
        #pragma unroll
        for (int e = 0; e < E_NUM; e++) s += expf(l[e] - m);
        g_tp[tok] = 1.0f / s;
        g_exp[tok] = arg;
        if (out_logits) {
            #pragma unroll
            for (int e = 0; e < E_NUM; e++)
                out_logits[(size_t)tok * E_NUM + e] = l[e];
        }
        if (out_idx) out_idx[tok] = (float)arg;
    }
}

// ---------------- kernel 2: single-CTA routing scan --------------------------
__global__ void __launch_bounds__(1024) k_scan() {
    __shared__ int scnt[E_NUM], sbase[E_NUM], soff[E_NUM], spc[E_NUM];
    const int tid = threadIdx.x;
    if (tid < E_NUM) scnt[tid] = 0;
    __syncthreads();
    for (int t = tid; t < T_TOK; t += 1024) atomicAdd(&scnt[g_exp[t]], 1);
    __syncthreads();
    if (tid == 0) {
        int s = 0;
        for (int e = 0; e < E_NUM; e++) {
            int c = scnt[e];
            int p = (c + 127) & ~127;
            g_cnt[e] = c; g_off[e] = s; g_pcnt[e] = p;
            soff[e] = s; spc[e] = p; sbase[e] = s;
            s += p;
        }
    }
    __syncthreads();
    for (int t = tid; t < T_TOK; t += 1024) {
        int e = g_exp[t];
        int d = atomicAdd(&sbase[e], 1);
        g_rowtok[d] = t;
        g_rowtp[d] = g_tp[t];
    }
    __syncthreads();
    for (int e = 0; e < E_NUM; e++) {
        int st = soff[e] + scnt[e], en = soff[e] + spc[e];
        for (int rr = st + tid; rr < en; rr += 1024) {
            g_rowtok[rr] = -1;
            g_rowtp[rr] = 0.0f;
        }
    }
}

// ---------------- fp16 mma.sync grouped GEMM --------------------------------
// CTA tile 128x128, K-chunk 64 elems (128B rows). 8 warps 2(M)x4(N), 64x32.
// SMEM per buf 32KB (A@0, B@16384); bufs at 0/32768.
// aux: rowtok@65536 (512B), rowtp@66048 (512B).
#define SM_RT  65536
#define SM_RP  66048
#define SM_DYN 67584   // 66560 + 1KB alignment slack

template<int KDIM, bool G1>
__global__ void __launch_bounds__(256, 2)
k_mma(const float* __restrict__ hidden, float* __restrict__ out) {
    const int e = blockIdx.z;
    const int m0 = blockIdx.y * 128;
    if (m0 >= g_pcnt[e]) return;
    const int n0 = blockIdx.x * 128;
    const int mbase = g_off[e] + m0;

    extern __shared__ char smem[];
    const uint32_t sb_raw = smem_u32(smem);
    const uint32_t sb0 = (sb_raw + 1023u) & ~1023u;
    char* sp = smem + (sb0 - sb_raw);

    const int tid = threadIdx.x;
    const int wid = tid >> 5, lane = tid & 31;
    const int wm = (wid & 1) * 64, wn = (wid >> 1) * 32;

    if (tid < 128) {
        reinterpret_cast<int*>(sp + SM_RT)[tid] = g_rowtok[mbase + tid];
        reinterpret_cast<float*>(sp + SM_RP)[tid] = g_rowtp[mbase + tid];
    }
    __syncthreads();

    // cp.async geometry: thread owns row r, 64B half of the 128B row
    const int r = tid >> 1, hf = tid & 1;
    uint32_t swo[4];
    #pragma unroll
    for (int i = 0; i < 4; i++) {
        uint32_t bo = r * 128 + hf * 64 + i * 16;
        swo[i] = bo ^ ((bo >> 3) & 0x70);
    }

    const __half *Ag, *Bg;
    uint32_t asz = 16;  // cp.async src bytes for A (0 => zero-fill pad row)
    if (G1) {
        const int tokA = reinterpret_cast<int*>(sp + SM_RT)[r];
        Ag = g_Xtok + (size_t)(tokA >= 0 ? tokA : 0) * D_DIM + hf * 32;
        asz = (tokA >= 0) ? 16u : 0u;
        Bg = g_wiT + ((size_t)e * F_DIM + n0 + r) * D_DIM + hf * 32;
    } else {
        Ag = g_H + (size_t)(mbase + r) * F_DIM + hf * 32;
        Bg = g_woT + ((size_t)e * D_DIM + n0 + r) * F_DIM + hf * 32;
    }

    float acc[4][4][4];
    #pragma unroll
    for (int mi = 0; mi < 4; mi++)
        #pragma unroll
        for (int ni = 0; ni < 4; ni++)
            #pragma unroll
            for (int q = 0; q < 4; q++) acc[mi][ni][q] = 0.0f;

    // ldmatrix per-lane geometry
    const int aRow = lane & 15;
    const int aKB = (lane >> 4) * 16;
    const int bRow = lane & 7;
    const int bKB = ((lane >> 3) & 1) * 16;

    auto issue = [&](int c) {
        const uint32_t bb = sb0 + (uint32_t)(c & 1) * 32768u;
        const int ko = c * 64;
        const char* sa = reinterpret_cast<const char*>(Ag + ko);
        const char* sb = reinterpret_cast<const char*>(Bg + ko);
        #pragma unroll
        for (int i = 0; i < 4; i++) {
            CP16Z(bb + 0     + swo[i], sa + i * 16, asz);
            CP16(bb + 16384 + swo[i], sb + i * 16);
        }
        CP_COMMIT();
    };

    constexpr int NCH = KDIM / 64;
    issue(0);

    #pragma unroll 1
    for (int c = 0; c < NCH; c++) {
        if (c + 1 < NCH) { issue(c + 1); CP_WAIT1(); }
        else             { CP_WAIT0(); }
        __syncthreads();

        const uint32_t bb = sb0 + (uint32_t)(c & 1) * 32768u;
        #pragma unroll
        for (int s = 0; s < 4; s++) {
            const int kb = s * 32;
            uint32_t ah[4][4], bh[4][2];
            #pragma unroll
            for (int mi = 0; mi < 4; mi++) {
                int row = wm + mi * 16 + aRow;
                uint32_t ad = bb + row * 128 + ((kb + aKB) ^ ((row & 7) << 4));
                LDSM4(ah[mi][0], ah[mi][1], ah[mi][2], ah[mi][3], ad);
            }
            #pragma unroll
            for (int ni = 0; ni < 4; ni++) {
                int row = wn + ni * 8 + bRow;
                uint32_t bd = bb + 16384 + row * 128 + ((kb + bKB) ^ ((row & 7) << 4));
                LDSM2(bh[ni][0], bh[ni][1], bd);
            }
            #pragma unroll
            for (int mi = 0; mi < 4; mi++)
                #pragma unroll
                for (int ni = 0; ni < 4; ni++)
                    MMA_F16(acc[mi][ni], ah[mi], bh[ni]);
        }
        __syncthreads();
    }

    // epilogue. acc[mi][ni]: rows (wm+mi*16+lane/4, +8), cols wn+ni*8+(lane&3)*2,+1
    if (G1) {
        #pragma unroll
        for (int mi = 0; mi < 4; mi++) {
            const size_t r0g = (size_t)(mbase + wm + mi * 16 + (lane >> 2));
            #pragma unroll
            for (int ni = 0; ni < 4; ni++) {
                const int col = n0 + wn + ni * 8 + (lane & 3) * 2;
                *reinterpret_cast<__half2*>(g_H + r0g * F_DIM + col) =
                    __floats2half2_rn(fmaxf(acc[mi][ni][0], 0.0f),
                                      fmaxf(acc[mi][ni][1], 0.0f));
                *reinterpret_cast<__half2*>(g_H + (r0g + 8) * F_DIM + col) =
                    __floats2half2_rn(fmaxf(acc[mi][ni][2], 0.0f),
                                      fmaxf(acc[mi][ni][3], 0.0f));
            }
        }
    } else {
        #pragma unroll
        for (int mi = 0; mi < 4; mi++) {
            const int idx = wm + mi * 16 + (lane >> 2);
            const int t0 = reinterpret_cast<int*>(sp + SM_RT)[idx];
            const int t1 = reinterpret_cast<int*>(sp + SM_RT)[idx + 8];
            const float p0 = reinterpret_cast<float*>(sp + SM_RP)[idx];
            const float p1 = reinterpret_cast<float*>(sp + SM_RP)[idx + 8];
            #pragma unroll
            for (int ni = 0; ni < 4; ni++) {
                const int col = n0 + wn + ni * 8 + (lane & 3) * 2;
                if (t0 >= 0) {
                    const size_t o = (size_t)t0 * D_DIM + col;
                    float2 h = *reinterpret_cast<const float2*>(hidden + o);
                    *reinterpret_cast<float2*>(out + o) =
                        make_float2(h.x + p0 * acc[mi][ni][0],
                                    h.y + p0 * acc[mi][ni][1]);
                }
                if (t1 >= 0) {
                    const size_t o = (size_t)t1 * D_DIM + col;
                    float2 h = *reinterpret_cast<const float2*>(hidden + o);
                    *reinterpret_cast<float2*>(out + o) =
                        make_float2(h.x + p1 * acc[mi][ni][2],
                                    h.y + p1 * acc[mi][ni][3]);
                }
            }
        }
    }
}

// ---------------- launch ----------------------------------------------------
extern "C" void kernel_launch(void* const* d_in, const int* in_sizes, int n_in,
                              void* d_out, int out_size) {
    const float* hidden = (const float*)d_in[0];
    const float* lnw    = (const float*)d_in[1];
    const float* rw     = (const float*)d_in[2];
    const float* wi     = (const float*)d_in[3];
    const float* wo     = (const float*)d_in[4];
    float* out = (float*)d_out;

    const int main_sz = T_TOK * D_DIM;
    float* out_logits = nullptr;
    float* out_idx = nullptr;
    if (out_size >= main_sz + T_TOK * E_NUM)
        out_logits = out + main_sz;
    if (out_size >= main_sz + T_TOK * E_NUM + T_TOK)
        out_idx = out + main_sz + T_TOK * E_NUM;

    static bool attr_done = false;
    if (!attr_done) {
        cudaFuncSetAttribute(k_mma<D_DIM, true>,
                             cudaFuncAttributeMaxDynamicSharedMemorySize, SM_DYN);
        cudaFuncSetAttribute(k_mma<F_DIM, false>,
                             cudaFuncAttributeMaxDynamicSharedMemorySize, SM_DYN);
        attr_done = true;
    }

    k_prep<<<WI_TILES + WO_TILES + T_TOK, 256>>>(hidden, lnw, rw, wi, wo,
                                                 out_logits, out_idx);
    k_scan<<<1, 1024>>>();
    k_mma<D_DIM, true><<<dim3(F_DIM / 128, T_TOK / 128, E_NUM), 256, SM_DYN>>>(nullptr, nullptr);
    k_mma<F_DIM, false><<<dim3(D_DIM / 128, T_TOK / 128, E_NUM), 256, SM_DYN>>>(hidden, out);
}

// round 9
// speedup vs baseline: 4.8741x; 1.0067x over previous
#include <cuda_runtime.h>
#include <cuda_fp16.h>
#include <cstdint>

// Problem: B=8,S=2048 -> T=16384 tokens, D=1024, F=4096, E=8
// R9: 3-stage cp.async pipeline, ONE __syncthreads per k-chunk (was 2 + tighter
// double buffer). Targets the barrier-stall diagnosis: tensor=44.9%,
// issue=15.6%, DRAM=6.9% on R8's k_mma. Everything else unchanged from R8.
// Keep `#pragma unroll 1` on the mainloop (R7: full unroll -> ptxas blowup).
#define T_TOK 16384
#define D_DIM 1024
#define F_DIM 4096
#define E_NUM 8
#define EPSV  1e-6f
#define MP_MAX 17408

// ---------------- device-global scratch (no runtime allocation) -------------
__device__ float g_tp[T_TOK];
__device__ int   g_exp[T_TOK];
__device__ int   g_cnt[E_NUM];
__device__ int   g_pcnt[E_NUM];
__device__ int   g_off[E_NUM];
__device__ int   g_rowtok[MP_MAX];
__device__ float g_rowtp[MP_MAX];
__device__ __half g_Xtok[(size_t)T_TOK * D_DIM];            // token-indexed fp16 X
__device__ __half g_H[(size_t)MP_MAX * F_DIM];              // expert-row fp16 H
__device__ __half g_wiT[(size_t)E_NUM * F_DIM * D_DIM];     // [E][F][D]
__device__ __half g_woT[(size_t)E_NUM * D_DIM * F_DIM];     // [E][D][F]

// ---------------- PTX helpers ----------------------------------------------
__device__ __forceinline__ uint32_t smem_u32(const void* p) {
    uint32_t a;
    asm("{ .reg .u64 t; cvta.to.shared.u64 t, %1; cvt.u32.u64 %0, t; }" : "=r"(a) : "l"(p));
    return a;
}
#define CP16(dst, src) \
    asm volatile("cp.async.cg.shared.global [%0], [%1], 16;" :: "r"(dst), "l"(src))
#define CP16Z(dst, src, sz) \
    asm volatile("cp.async.cg.shared.global [%0], [%1], 16, %2;" \
                 :: "r"(dst), "l"(src), "r"(sz))
#define CP_COMMIT() asm volatile("cp.async.commit_group;" ::: "memory")
#define CP_WAIT1()  asm volatile("cp.async.wait_group 1;" ::: "memory")
#define CP_WAIT0()  asm volatile("cp.async.wait_group 0;" ::: "memory")
#define LDSM4(r0, r1, r2, r3, addr) \
    asm volatile("ldmatrix.sync.aligned.m8n8.x4.shared.b16 {%0,%1,%2,%3}, [%4];" \
                 : "=r"(r0), "=r"(r1), "=r"(r2), "=r"(r3) : "r"(addr))
#define LDSM2(r0, r1, addr) \
    asm volatile("ldmatrix.sync.aligned.m8n8.x2.shared.b16 {%0,%1}, [%2];" \
                 : "=r"(r0), "=r"(r1) : "r"(addr))
#define MMA_F16(d, a, b) \
    asm volatile("mma.sync.aligned.m16n8k16.row.col.f32.f16.f16.f32 " \
                 "{%0,%1,%2,%3}, {%4,%5,%6,%7}, {%8,%9}, {%0,%1,%2,%3};" \
                 : "+f"((d)[0]), "+f"((d)[1]), "+f"((d)[2]), "+f"((d)[3]) \
                 : "r"((a)[0]), "r"((a)[1]), "r"((a)[2]), "r"((a)[3]), \
                   "r"((b)[0]), "r"((b)[1]))

// ---------------- kernel 1: fused weight transpose + RMSNorm/router ---------
#define WI_TILES 32768   // (F/32)*(D/32)*E
#define WO_TILES 32768   // (D/32)*(F/32)*E
__global__ void __launch_bounds__(256)
k_prep(const float* __restrict__ x,
       const float* __restrict__ lnw,
       const float* __restrict__ rw,
       const float* __restrict__ wi,
       const float* __restrict__ wo,
       float* __restrict__ out_logits,
       float* __restrict__ out_idx) {
    __shared__ float shbuf[32 * 33];
    const int b = blockIdx.x;
    const int tid = threadIdx.x;

    if (b < WI_TILES + WO_TILES) {
        const bool is_wi = (b < WI_TILES);
        const int bb = is_wi ? b : b - WI_TILES;
        const int R = is_wi ? D_DIM : F_DIM;
        const int C = is_wi ? F_DIM : D_DIM;
        const int ctiles = C / 32;
        const int e = bb / (ctiles * (R / 32));
        const int rem = bb % (ctiles * (R / 32));
        const int cx = rem % ctiles, ry = rem / ctiles;
        const int c0 = cx * 32, r0 = ry * 32;
        const float* ip = (is_wi ? wi : wo) + (size_t)e * R * C;
        __half* op = (is_wi ? g_wiT : g_woT) + (size_t)e * R * C;
        const int tx = tid & 31, ty = tid >> 5;  // 32 x 8
        #pragma unroll
        for (int j = 0; j < 4; j++)
            shbuf[(ty + 8 * j) * 33 + tx] = ip[(size_t)(r0 + ty + 8 * j) * C + c0 + tx];
        __syncthreads();
        #pragma unroll
        for (int j = 0; j < 4; j++)
            op[(size_t)(c0 + ty + 8 * j) * R + r0 + tx] =
                __float2half(shbuf[tx * 33 + ty + 8 * j]);
        return;
    }

    const int tok = b - (WI_TILES + WO_TILES);
    const int lane = tid & 31, wrp = tid >> 5;
    const size_t base = (size_t)tok * D_DIM + tid * 4;
    float4 v = *reinterpret_cast<const float4*>(x + base);

    float ss = v.x * v.x + v.y * v.y + v.z * v.z + v.w * v.w;
    #pragma unroll
    for (int o = 16; o > 0; o >>= 1) ss += __shfl_xor_sync(0xFFFFFFFFu, ss, o);
    if (lane == 0) shbuf[wrp] = ss;
    __syncthreads();
    float var = 0.0f;
    #pragma unroll
    for (int w = 0; w < 8; w++) var += shbuf[w];
    var *= (1.0f / D_DIM);
    const float rs = rsqrtf(var + EPSV);

    float4 w4 = *reinterpret_cast<const float4*>(lnw + tid * 4);
    float n[4] = {v.x * rs * w4.x, v.y * rs * w4.y, v.z * rs * w4.z, v.w * rs * w4.w};

    __half2 h01 = __floats2half2_rn(n[0], n[1]);
    __half2 h23 = __floats2half2_rn(n[2], n[3]);
    *reinterpret_cast<__half2*>(g_Xtok + base) = h01;
    *reinterpret_cast<__half2*>(g_Xtok + base + 2) = h23;

    float acc[E_NUM];
    #pragma unroll
    for (int e = 0; e < E_NUM; e++) acc[e] = 0.0f;
    #pragma unroll
    for (int i = 0; i < 4; i++) {
        const float* r = rw + (size_t)(tid * 4 + i) * E_NUM;
        float4 r0 = *reinterpret_cast<const float4*>(r);
        float4 r1 = *reinterpret_cast<const float4*>(r + 4);
        acc[0] += n[i] * r0.x;  acc[1] += n[i] * r0.y;
        acc[2] += n[i] * r0.z;  acc[3] += n[i] * r0.w;
        acc[4] += n[i] * r1.x;  acc[5] += n[i] * r1.y;
        acc[6] += n[i] * r1.z;  acc[7] += n[i] * r1.w;
    }
    #pragma unroll
    for (int e = 0; e < E_NUM; e++) {
        #pragma unroll
        for (int o = 16; o > 0; o >>= 1)
            acc[e] += __shfl_xor_sync(0xFFFFFFFFu, acc[e], o);
    }
    __syncthreads();
    if (lane == 0) {
        #pragma unroll
        for (int e = 0; e < E_NUM; e++) shbuf[32 + wrp * E_NUM + e] = acc[e];
    }
    __syncthreads();
    if (tid == 0) {
        float l[E_NUM];
        #pragma unroll
        for (int e = 0; e < E_NUM; e++) {
            float s = 0.0f;
            #pragma unroll
            for (int w = 0; w < 8; w++) s += shbuf[32 + w * E_NUM + e];
            l[e] = s;
        }
        float m = l[0];
        int arg = 0;
        #pragma unroll
        for (int e = 1; e < E_NUM; e++)
            if (l[e] > m) { m = l[e]; arg = e; }
        float s = 0.0f;
        #pragma unroll
        for (int e = 0; e < E_NUM; e++) s += expf(l[e] - m);
        g_tp[tok] = 1.0f / s;
        g_exp[tok] = arg;
        if (out_logits) {
            #pragma unroll
            for (int e = 0; e < E_NUM; e++)
                out_logits[(size_t)tok * E_NUM + e] = l[e];
        }
        if (out_idx) out_idx[tok] = (float)arg;
    }
}

// ---------------- kernel 2: single-CTA routing scan --------------------------
__global__ void __launch_bounds__(1024) k_scan() {
    __shared__ int scnt[E_NUM], sbase[E_NUM], soff[E_NUM], spc[E_NUM];
    const int tid = threadIdx.x;
    if (tid < E_NUM) scnt[tid] = 0;
    __syncthreads();
    for (int t = tid; t < T_TOK; t += 1024) atomicAdd(&scnt[g_exp[t]], 1);
    __syncthreads();
    if (tid == 0) {
        int s = 0;
        for (int e = 0; e < E_NUM; e++) {
            int c = scnt[e];
            int p = (c + 127) & ~127;
            g_cnt[e] = c; g_off[e] = s; g_pcnt[e] = p;
            soff[e] = s; spc[e] = p; sbase[e] = s;
            s += p;
        }
    }
    __syncthreads();
    for (int t = tid; t < T_TOK; t += 1024) {
        int e = g_exp[t];
        int d = atomicAdd(&sbase[e], 1);
        g_rowtok[d] = t;
        g_rowtp[d] = g_tp[t];
    }
    __syncthreads();
    for (int e = 0; e < E_NUM; e++) {
        int st = soff[e] + scnt[e], en = soff[e] + spc[e];
        for (int rr = st + tid; rr < en; rr += 1024) {
            g_rowtok[rr] = -1;
            g_rowtp[rr] = 0.0f;
        }
    }
}

// ---------------- fp16 mma.sync grouped GEMM, 3-stage pipeline ---------------
// CTA tile 128x128, K-chunk 64 elems (128B rows). 8 warps 2(M)x4(N), 64x32.
// SMEM: 3 bufs x 32KB (A@0, B@16384 within buf) at 0/32768/65536.
// aux: rowtok@98304 (512B), rowtp@98816 (512B).
#define SM_RT  98304
#define SM_RP  98816
#define SM_DYN 100352   // 99328 + 1KB alignment slack

template<int KDIM, bool G1>
__global__ void __launch_bounds__(256, 2)
k_mma(const float* __restrict__ hidden, float* __restrict__ out) {
    const int e = blockIdx.z;
    const int m0 = blockIdx.y * 128;
    if (m0 >= g_pcnt[e]) return;
    const int n0 = blockIdx.x * 128;
    const int mbase = g_off[e] + m0;

    extern __shared__ char smem[];
    const uint32_t sb_raw = smem_u32(smem);
    const uint32_t sb0 = (sb_raw + 1023u) & ~1023u;
    char* sp = smem + (sb0 - sb_raw);

    const int tid = threadIdx.x;
    const int wid = tid >> 5, lane = tid & 31;
    const int wm = (wid & 1) * 64, wn = (wid >> 1) * 32;

    if (tid < 128) {
        reinterpret_cast<int*>(sp + SM_RT)[tid] = g_rowtok[mbase + tid];
        reinterpret_cast<float*>(sp + SM_RP)[tid] = g_rowtp[mbase + tid];
    }
    __syncthreads();

    // cp.async geometry: thread owns row r, 64B half of the 128B row
    const int r = tid >> 1, hf = tid & 1;
    uint32_t swo[4];
    #pragma unroll
    for (int i = 0; i < 4; i++) {
        uint32_t bo = r * 128 + hf * 64 + i * 16;
        swo[i] = bo ^ ((bo >> 3) & 0x70);
    }

    const __half *Ag, *Bg;
    uint32_t asz = 16;
    if (G1) {
        const int tokA = reinterpret_cast<int*>(sp + SM_RT)[r];
        Ag = g_Xtok + (size_t)(tokA >= 0 ? tokA : 0) * D_DIM + hf * 32;
        asz = (tokA >= 0) ? 16u : 0u;
        Bg = g_wiT + ((size_t)e * F_DIM + n0 + r) * D_DIM + hf * 32;
    } else {
        Ag = g_H + (size_t)(mbase + r) * F_DIM + hf * 32;
        Bg = g_woT + ((size_t)e * D_DIM + n0 + r) * F_DIM + hf * 32;
    }

    float acc[4][4][4];
    #pragma unroll
    for (int mi = 0; mi < 4; mi++)
        #pragma unroll
        for (int ni = 0; ni < 4; ni++)
            #pragma unroll
            for (int q = 0; q < 4; q++) acc[mi][ni][q] = 0.0f;

    const int aRow = lane & 15;
    const int aKB = (lane >> 4) * 16;
    const int bRow = lane & 7;
    const int bKB = ((lane >> 3) & 1) * 16;

    auto issue = [&](int c) {
        const uint32_t bb = sb0 + (uint32_t)(c % 3) * 32768u;
        const int ko = c * 64;
        const char* sa = reinterpret_cast<const char*>(Ag + ko);
        const char* sb = reinterpret_cast<const char*>(Bg + ko);
        #pragma unroll
        for (int i = 0; i < 4; i++) {
            CP16Z(bb + 0     + swo[i], sa + i * 16, asz);
            CP16(bb + 16384 + swo[i], sb + i * 16);
        }
        CP_COMMIT();
    };

    constexpr int NCH = KDIM / 64;
    issue(0);
    issue(1);

    // One __syncthreads per chunk: the barrier at iter c proves all warps
    // finished compute(c-1), so refilling buffer (c+2)%3 (last held c-1) is safe.
    #pragma unroll 1
    for (int c = 0; c < NCH; c++) {
        if (c + 1 < NCH) CP_WAIT1(); else CP_WAIT0();
        __syncthreads();
        if (c + 2 < NCH) issue(c + 2);

        const uint32_t bb = sb0 + (uint32_t)(c % 3) * 32768u;
        #pragma unroll
        for (int s = 0; s < 4; s++) {
            const int kb = s * 32;
            uint32_t ah[4][4], bh[4][2];
            #pragma unroll
            for (int mi = 0; mi < 4; mi++) {
                int row = wm + mi * 16 + aRow;
                uint32_t ad = bb + row * 128 + ((kb + aKB) ^ ((row & 7) << 4));
                LDSM4(ah[mi][0], ah[mi][1], ah[mi][2], ah[mi][3], ad);
            }
            #pragma unroll
            for (int ni = 0; ni < 4; ni++) {
                int row = wn + ni * 8 + bRow;
                uint32_t bd = bb + 16384 + row * 128 + ((kb + bKB) ^ ((row & 7) << 4));
                LDSM2(bh[ni][0], bh[ni][1], bd);
            }
            #pragma unroll
            for (int mi = 0; mi < 4; mi++)
                #pragma unroll
                for (int ni = 0; ni < 4; ni++)
                    MMA_F16(acc[mi][ni], ah[mi], bh[ni]);
        }
    }

    // epilogue. acc[mi][ni]: rows (wm+mi*16+lane/4, +8), cols wn+ni*8+(lane&3)*2,+1
    if (G1) {
        #pragma unroll
        for (int mi = 0; mi < 4; mi++) {
            const size_t r0g = (size_t)(mbase + wm + mi * 16 + (lane >> 2));
            #pragma unroll
            for (int ni = 0; ni < 4; ni++) {
                const int col = n0 + wn + ni * 8 + (lane & 3) * 2;
                *reinterpret_cast<__half2*>(g_H + r0g * F_DIM + col) =
                    __floats2half2_rn(fmaxf(acc[mi][ni][0], 0.0f),
                                      fmaxf(acc[mi][ni][1], 0.0f));
                *reinterpret_cast<__half2*>(g_H + (r0g + 8) * F_DIM + col) =
                    __floats2half2_rn(fmaxf(acc[mi][ni][2], 0.0f),
                                      fmaxf(acc[mi][ni][3], 0.0f));
            }
        }
    } else {
        #pragma unroll
        for (int mi = 0; mi < 4; mi++) {
            const int idx = wm + mi * 16 + (lane >> 2);
            const int t0 = reinterpret_cast<int*>(sp + SM_RT)[idx];
            const int t1 = reinterpret_cast<int*>(sp + SM_RT)[idx + 8];
            const float p0 = reinterpret_cast<float*>(sp + SM_RP)[idx];
            const float p1 = reinterpret_cast<float*>(sp + SM_RP)[idx + 8];
            #pragma unroll
            for (int ni = 0; ni < 4; ni++) {
                const int col = n0 + wn + ni * 8 + (lane & 3) * 2;
                if (t0 >= 0) {
                    const size_t o = (size_t)t0 * D_DIM + col;
                    float2 h = *reinterpret_cast<const float2*>(hidden + o);
                    *reinterpret_cast<float2*>(out + o) =
                        make_float2(h.x + p0 * acc[mi][ni][0],
                                    h.y + p0 * acc[mi][ni][1]);
                }
                if (t1 >= 0) {
                    const size_t o = (size_t)t1 * D_DIM + col;
                    float2 h = *reinterpret_cast<const float2*>(hidden + o);
                    *reinterpret_cast<float2*>(out + o) =
                        make_float2(h.x + p1 * acc[mi][ni][2],
                                    h.y + p1 * acc[mi][ni][3]);
                }
            }
        }
    }
}

// ---------------- launch ----------------------------------------------------
extern "C" void kernel_launch(void* const* d_in, const int* in_sizes, int n_in,
                              void* d_out, int out_size) {
    const float* hidden = (const float*)d_in[0];
    const float* lnw    = (const float*)d_in[1];
    const float* rw     = (const float*)d_in[2];
    const float* wi     = (const float*)d_in[3];
    const float* wo     = (const float*)d_in[4];
    float* out = (float*)d_out;

    const int main_sz = T_TOK * D_DIM;
    float* out_logits = nullptr;
    float* out_idx = nullptr;
    if (out_size >= main_sz + T_TOK * E_NUM)
        out_logits = out + main_sz;
    if (out_size >= main_sz + T_TOK * E_NUM + T_TOK)
        out_idx = out + main_sz + T_TOK * E_NUM;

    static bool attr_done = false;
    if (!attr_done) {
        cudaFuncSetAttribute(k_mma<D_DIM, true>,
                             cudaFuncAttributeMaxDynamicSharedMemorySize, SM_DYN);
        cudaFuncSetAttribute(k_mma<F_DIM, false>,
                             cudaFuncAttributeMaxDynamicSharedMemorySize, SM_DYN);
        attr_done = true;
    }

    k_prep<<<WI_TILES + WO_TILES + T_TOK, 256>>>(hidden, lnw, rw, wi, wo,
                                                 out_logits, out_idx);
    k_scan<<<1, 1024>>>();
    k_mma<D_DIM, true><<<dim3(F_DIM / 128, T_TOK / 128, E_NUM), 256, SM_DYN>>>(nullptr, nullptr);
    k_mma<F_DIM, false><<<dim3(D_DIM / 128, T_TOK / 128, E_NUM), 256, SM_DYN>>>(hidden, out);
}